// round 2
// baseline (speedup 1.0000x reference)
#include <cuda_runtime.h>
#include <math.h>

#define N_VAR 50000
#define N_CLA 100000
#define NM    150000
#define DD    64
#define NC    1000
#define VC    64
#define KCL   128
#define NN    192      // nodes per cluster = VC + KCL
#define NE    8000
#define NSH   8
#define NITER 3
#define NEG   0.2f
#define GAMMA 1.0f
#define INVSCALE 0.125f   // 1/sqrt(64)
#define KST   68          // smem row stride (floats): conflict-free for float4 patterns
#define KST4  17          // row stride in float4

// ---------------- scratch (static device globals; no runtime alloc) ----------
__device__ float g_x  [NM * DD];   // [vars | clauses]
__device__ float g_Q  [NM * DD];
__device__ float g_K  [NM * DD];
__device__ float g_V  [NM * DD];
__device__ float g_acc[NM * DD];
__device__ float g_cnt[NM];
__device__ float g_Q2 [NC * DD];
__device__ float g_K2 [NC * DD];
__device__ float g_V2 [NC * DD];
__device__ float g_pool[2 * DD];

// ---------------- init: pack x_var / x_clause into g_x -----------------------
__global__ void k_init(const float* __restrict__ xv, const float* __restrict__ xc) {
    int stride = gridDim.x * blockDim.x;
    for (int i = blockIdx.x * blockDim.x + threadIdx.x; i < NM * DD; i += stride)
        g_x[i] = (i < N_VAR * DD) ? xv[i] : xc[i - N_VAR * DD];
}

__global__ void k_poolzero() {
    if (threadIdx.x < 2 * DD) g_pool[threadIdx.x] = 0.f;
}

// ---------------- Q/K/V projection: y = x @ W^T + zero g_acc/g_cnt ----------
// 64 rows per block, warp-per-row. Weights in smem [d][k] stride 68; float4 LDS.
__global__ void k_proj(const float* __restrict__ WQ,
                       const float* __restrict__ WK,
                       const float* __restrict__ WV) {
    extern __shared__ float sm[];
    float* Wt = sm;                   // 3 * 64 * KST
    float* xs = sm + 3 * 64 * KST;    // 8 * 64
    int tid = threadIdx.x;
    for (int i = tid; i < 64 * 64; i += 256) {
        int d = i >> 6, k = i & 63;
        Wt[0 * 64 * KST + d * KST + k] = WQ[i];
        Wt[1 * 64 * KST + d * KST + k] = WK[i];
        Wt[2 * 64 * KST + d * KST + k] = WV[i];
    }
    __syncthreads();
    int warp = tid >> 5, lane = tid & 31;
    float* xw = xs + warp * 64;
    const float4* xw4 = (const float4*)xw;
    const float4* W4  = (const float4*)Wt;   // row stride KST4
    for (int rr = 0; rr < 8; rr++) {
        int r = blockIdx.x * 64 + rr * 8 + warp;
        if (r >= NM) continue;
        const float* xr = g_x + (size_t)r * DD;
        xw[lane]      = xr[lane];
        xw[lane + 32] = xr[lane + 32];
        __syncwarp();
        float a0 = 0, a1 = 0, a2 = 0, a3 = 0, a4 = 0, a5 = 0;
        #pragma unroll
        for (int k4 = 0; k4 < 16; k4++) {
            float4 x = xw4[k4];
            float4 w;
            w = W4[(lane)       * KST4 + k4]; a0 = fmaf(x.x,w.x,fmaf(x.y,w.y,fmaf(x.z,w.z,fmaf(x.w,w.w,a0))));
            w = W4[(lane+32)    * KST4 + k4]; a1 = fmaf(x.x,w.x,fmaf(x.y,w.y,fmaf(x.z,w.z,fmaf(x.w,w.w,a1))));
            w = W4[(64+lane)    * KST4 + k4]; a2 = fmaf(x.x,w.x,fmaf(x.y,w.y,fmaf(x.z,w.z,fmaf(x.w,w.w,a2))));
            w = W4[(64+lane+32) * KST4 + k4]; a3 = fmaf(x.x,w.x,fmaf(x.y,w.y,fmaf(x.z,w.z,fmaf(x.w,w.w,a3))));
            w = W4[(128+lane)   * KST4 + k4]; a4 = fmaf(x.x,w.x,fmaf(x.y,w.y,fmaf(x.z,w.z,fmaf(x.w,w.w,a4))));
            w = W4[(128+lane+32)* KST4 + k4]; a5 = fmaf(x.x,w.x,fmaf(x.y,w.y,fmaf(x.z,w.z,fmaf(x.w,w.w,a5))));
        }
        size_t o = (size_t)r * DD;
        g_Q[o + lane] = a0; g_Q[o + lane + 32] = a1;
        g_K[o + lane] = a2; g_K[o + lane + 32] = a3;
        g_V[o + lane] = a4; g_V[o + lane + 32] = a5;
        g_acc[o + lane] = 0.f; g_acc[o + lane + 32] = 0.f;
        if (lane == 0) g_cnt[r] = 0.f;
        __syncwarp();
    }
}

// ---------------- intra-cluster attention (GAT1 core) ------------------------
// 2 CTAs per cluster (96 queries each). K,V tiles in SMEM stride 68 (float4
// conflict-free). Softmax weights stay in registers; shfl-redistributed.
__global__ void k_attn(const int* __restrict__ cvar, const int* __restrict__ ccla,
                       const float* __restrict__ sat, const float* __restrict__ hw) {
    extern __shared__ float sm[];
    float* Ksh = sm;                    // NN*KST
    float* Vsh = Ksh + NN * KST;        // NN*KST
    float* qsh = Vsh + NN * KST;        // 8*64
    float* bsh = qsh + 8 * 64;          // NN
    int*   nsh = (int*)(bsh + NN);      // NN

    int bx = blockIdx.x;
    int c = bx >> 1, qhalf = bx & 1;
    int tid = threadIdx.x;
    if (tid < NN) {
        int g; float b;
        if (tid < VC) { g = cvar[c * VC + tid]; b = 0.f; }
        else { int cl = ccla[c * KCL + (tid - VC)]; g = N_VAR + cl; b = GAMMA * sat[cl]; }
        nsh[tid] = g; bsh[tid] = b;
    }
    __syncthreads();
    for (int i = tid; i < NN * DD; i += 256) {
        int j = i >> 6, d = i & 63;
        size_t o = (size_t)nsh[j] * DD + d;
        Ksh[j * KST + d] = g_K[o];
        Vsh[j * KST + d] = g_V[o];
    }
    float hwm = 0.25f * (hw[0] + hw[1] + hw[2] + hw[3]);
    __syncthreads();

    int warp = tid >> 5, lane = tid & 31;
    float* qw = qsh + warp * 64;
    const float4* Ksh4 = (const float4*)Ksh;
    const float4* Vsh4 = (const float4*)Vsh;
    const float4* qw4  = (const float4*)qw;
    int h16 = lane >> 4;        // 0/1: even/odd key half in output phase
    int l15 = lane & 15;        // float4 dim column

    int qbase = qhalf * 96;
    for (int i = qbase + warp; i < qbase + 96; i += 8) {
        int g = nsh[i];
        size_t qo = (size_t)g * DD;
        qw[lane]      = g_Q[qo + lane];
        qw[lane + 32] = g_Q[qo + lane + 32];
        __syncwarp();

        // ---- scores: lane owns keys jj*32+lane ----
        float acc[6] = {0.f, 0.f, 0.f, 0.f, 0.f, 0.f};
        #pragma unroll
        for (int d4 = 0; d4 < 16; d4++) {
            float4 q = qw4[d4];
            #pragma unroll
            for (int jj = 0; jj < 6; jj++) {
                float4 k = Ksh4[(jj * 32 + lane) * KST4 + d4];
                acc[jj] = fmaf(q.x, k.x, fmaf(q.y, k.y, fmaf(q.z, k.z, fmaf(q.w, k.w, acc[jj]))));
            }
        }
        // ---- bias + leaky_relu + softmax ----
        float m = -1e30f;
        #pragma unroll
        for (int jj = 0; jj < 6; jj++) {
            float s = acc[jj] * INVSCALE + bsh[jj * 32 + lane];
            s = (s >= 0.f) ? s : NEG * s;
            acc[jj] = s;
            m = fmaxf(m, s);
        }
        #pragma unroll
        for (int o = 16; o > 0; o >>= 1) m = fmaxf(m, __shfl_xor_sync(0xffffffffu, m, o));
        float ssum = 0.f;
        #pragma unroll
        for (int jj = 0; jj < 6; jj++) { acc[jj] = __expf(acc[jj] - m); ssum += acc[jj]; }
        #pragma unroll
        for (int o = 16; o > 0; o >>= 1) ssum += __shfl_xor_sync(0xffffffffu, ssum, o);
        float inv = 1.f / ssum;
        #pragma unroll
        for (int jj = 0; jj < 6; jj++) acc[jj] *= inv;

        // ---- output: lane half h16 handles even/odd keys; l15 owns dim quad ----
        float4 o4 = make_float4(0.f, 0.f, 0.f, 0.f);
        #pragma unroll
        for (int jj = 0; jj < 6; jj++) {
            #pragma unroll
            for (int ii = 0; ii < 16; ii++) {
                float w = __shfl_sync(0xffffffffu, acc[jj], 2 * ii + h16);
                float4 v = Vsh4[(jj * 32 + 2 * ii + h16) * KST4 + l15];
                o4.x = fmaf(w, v.x, o4.x);
                o4.y = fmaf(w, v.y, o4.y);
                o4.z = fmaf(w, v.z, o4.z);
                o4.w = fmaf(w, v.w, o4.w);
            }
        }
        o4.x += __shfl_xor_sync(0xffffffffu, o4.x, 16);
        o4.y += __shfl_xor_sync(0xffffffffu, o4.y, 16);
        o4.z += __shfl_xor_sync(0xffffffffu, o4.z, 16);
        o4.w += __shfl_xor_sync(0xffffffffu, o4.w, 16);
        if (lane < 16) {
            float* dst = g_acc + (size_t)g * DD + 4 * lane;
            atomicAdd(dst + 0, o4.x * hwm);
            atomicAdd(dst + 1, o4.y * hwm);
            atomicAdd(dst + 2, o4.z * hwm);
            atomicAdd(dst + 3, o4.w * hwm);
        }
        if (lane == 0) atomicAdd(&g_cnt[g], 1.f);
        __syncwarp();
    }
}

// ---------------- finalize: (acc/cnt) @ Wo^T + bo, residual add --------------
__global__ void k_fin(const float* __restrict__ Wo, const float* __restrict__ bo) {
    extern __shared__ float sm[];
    float* Wt = sm;               // 64*KST
    float* xs = Wt + 64 * KST;    // 8*64
    int tid = threadIdx.x;
    for (int i = tid; i < 64 * 64; i += 256) {
        int d = i >> 6, k = i & 63;
        Wt[d * KST + k] = Wo[i];
    }
    __syncthreads();
    int warp = tid >> 5, lane = tid & 31;
    float* xw = xs + warp * 64;
    const float4* xw4 = (const float4*)xw;
    const float4* W4  = (const float4*)Wt;
    float b0 = bo[lane], b1 = bo[lane + 32];
    for (int rr = 0; rr < 8; rr++) {
        int r = blockIdx.x * 64 + rr * 8 + warp;
        if (r >= NM) continue;
        float inv = 1.f / fmaxf(g_cnt[r], 1.f);
        size_t o = (size_t)r * DD;
        xw[lane]      = g_acc[o + lane] * inv;
        xw[lane + 32] = g_acc[o + lane + 32] * inv;
        __syncwarp();
        float y0 = b0, y1 = b1;
        #pragma unroll
        for (int k4 = 0; k4 < 16; k4++) {
            float4 a = xw4[k4];
            float4 w;
            w = W4[lane * KST4 + k4];
            y0 = fmaf(a.x, w.x, fmaf(a.y, w.y, fmaf(a.z, w.z, fmaf(a.w, w.w, y0))));
            w = W4[(lane + 32) * KST4 + k4];
            y1 = fmaf(a.x, w.x, fmaf(a.y, w.y, fmaf(a.z, w.z, fmaf(a.w, w.w, y1))));
        }
        g_x[o + lane]      += y0;
        g_x[o + lane + 32] += y1;
        __syncwarp();
    }
}

// ---------------- cluster features + Q2/K2/V2 projection ---------------------
__global__ void k_cf(const int* __restrict__ cvar,
                     const float* __restrict__ WQ2, const float* __restrict__ WK2,
                     const float* __restrict__ WV2) {
    __shared__ float cf[64];
    __shared__ int ids[64];
    int c = blockIdx.x, d = threadIdx.x;
    ids[d] = cvar[c * VC + d];
    __syncthreads();
    float s = 0.f;
    #pragma unroll 8
    for (int v = 0; v < VC; v++) s += g_x[(size_t)ids[v] * DD + d];
    cf[d] = s * (1.f / 64.f);
    __syncthreads();
    float q = 0.f, k = 0.f, v = 0.f;
    #pragma unroll 8
    for (int j = 0; j < 64; j++) {
        float x = cf[j];
        q = fmaf(x, WQ2[d * 64 + j], q);
        k = fmaf(x, WK2[d * 64 + j], k);
        v = fmaf(x, WV2[d * 64 + j], v);
    }
    g_Q2[c * 64 + d] = q; g_K2[c * 64 + d] = k; g_V2[c * 64 + d] = v;
}

// ---------------- inter-cluster edge scatter (GAT2) --------------------------
__global__ void k_edge(const int* __restrict__ ei, const int* __restrict__ shv,
                       const float* __restrict__ hw) {
    int tid = threadIdx.x;
    int warp = tid >> 5, lane = tid & 31;
    int e = blockIdx.x * 8 + warp;
    if (e >= NE) return;
    int c1 = ei[e], c2 = ei[NE + e];
    float p = g_Q2[c1 * 64 + lane] * g_K2[c2 * 64 + lane]
            + g_Q2[c1 * 64 + lane + 32] * g_K2[c2 * 64 + lane + 32];
    #pragma unroll
    for (int o = 16; o > 0; o >>= 1) p += __shfl_xor_sync(0xffffffffu, p, o);
    float s = p * INVSCALE;
    float lr = (s >= 0.f) ? s : NEG * s;
    float hwm = 0.25f * (hw[0] + hw[1] + hw[2] + hw[3]);
    float a = hwm / (1.f + __expf(-lr));
    float v0 = a * g_V2[c2 * 64 + lane];
    float v1 = a * g_V2[c2 * 64 + lane + 32];
    #pragma unroll
    for (int k = 0; k < NSH; k++) {
        int sv = shv[e * NSH + k];
        atomicAdd(&g_x[(size_t)sv * DD + lane],      v0);
        atomicAdd(&g_x[(size_t)sv * DD + lane + 32], v1);
    }
}

// ---------------- pooling + MLP readout --------------------------------------
__global__ void k_pool() {
    int tid = threadIdx.x;
    int col = tid & 63;
    int rg = tid >> 6;   // 0..3
    float sv = 0.f, sc = 0.f;
    for (int r = blockIdx.x * 4 + rg; r < NM; r += gridDim.x * 4) {
        float x = g_x[(size_t)r * DD + col];
        if (r < N_VAR) sv += x; else sc += x;
    }
    atomicAdd(&g_pool[col], sv);
    atomicAdd(&g_pool[64 + col], sc);
}

__global__ void k_mlp(const float* __restrict__ W1, const float* __restrict__ b1,
                      const float* __restrict__ W2, const float* __restrict__ b2,
                      float* __restrict__ out) {
    __shared__ float p[128];
    __shared__ float h[64];
    int tid = threadIdx.x;
    if (tid < 128)
        p[tid] = tanhf(g_pool[tid] * (tid < 64 ? 1.f / N_VAR : 1.f / N_CLA));
    __syncthreads();
    if (tid < 64) {
        float a = b1[tid];
        #pragma unroll 8
        for (int j = 0; j < 128; j++) a = fmaf(p[j], W1[tid * 128 + j], a);
        h[tid] = (a > 0.f) ? a : 0.f;
    }
    __syncthreads();
    if (tid == 0) {
        float s = b2[0];
        for (int i = 0; i < 64; i++) s = fmaf(h[i], W2[i], s);
        out[0] = s;
    }
}

// ---------------- launch ------------------------------------------------------
extern "C" void kernel_launch(void* const* d_in, const int* in_sizes, int n_in,
                              void* d_out, int out_size) {
    (void)in_sizes; (void)n_in; (void)out_size;
    const float* xv   = (const float*)d_in[0];
    const float* xc   = (const float*)d_in[1];
    const float* sat  = (const float*)d_in[2];
    const int*   cvar = (const int*)d_in[3];
    const int*   ccla = (const int*)d_in[4];
    const int*   ei   = (const int*)d_in[5];
    const int*   shv  = (const int*)d_in[6];
    const float* WQ1  = (const float*)d_in[7];
    const float* WK1  = (const float*)d_in[8];
    const float* WV1  = (const float*)d_in[9];
    const float* hw1  = (const float*)d_in[10];
    const float* Wo   = (const float*)d_in[11];
    const float* bo   = (const float*)d_in[12];
    const float* WQ2  = (const float*)d_in[13];
    const float* WK2  = (const float*)d_in[14];
    const float* WV2  = (const float*)d_in[15];
    const float* hw2  = (const float*)d_in[16];
    const float* W1   = (const float*)d_in[17];
    const float* b1   = (const float*)d_in[18];
    const float* W2   = (const float*)d_in[19];
    const float* b2   = (const float*)d_in[20];

    const int projSmem = (3 * 64 * KST + 8 * 64) * 4;                      // 54272
    const int attnSmem = (2 * NN * KST + 8 * 64 + NN) * 4 + NN * 4;        // 108032
    const int finSmem  = (64 * KST + 8 * 64) * 4;                          // 19456
    cudaFuncSetAttribute(k_proj, cudaFuncAttributeMaxDynamicSharedMemorySize, projSmem);
    cudaFuncSetAttribute(k_attn, cudaFuncAttributeMaxDynamicSharedMemorySize, attnSmem);
    cudaFuncSetAttribute(k_fin,  cudaFuncAttributeMaxDynamicSharedMemorySize, finSmem);

    k_init<<<512, 256>>>(xv, xc);
    const int rowBlocks = (NM + 63) / 64;
    for (int it = 0; it < NITER; it++) {
        k_proj<<<rowBlocks, 256, projSmem>>>(WQ1, WK1, WV1);   // also zeroes g_acc/g_cnt
        k_attn<<<2 * NC, 256, attnSmem>>>(cvar, ccla, sat, hw1);
        k_fin<<<rowBlocks, 256, finSmem>>>(Wo, bo);
        k_cf<<<NC, 64>>>(cvar, WQ2, WK2, WV2);
        k_edge<<<(NE + 7) / 8, 256>>>(ei, shv, hw2);
    }
    k_poolzero<<<1, 128>>>();
    k_pool<<<512, 256>>>();
    k_mlp<<<1, 128>>>(W1, b1, W2, b2, (float*)d_out);
}

// round 3
// speedup vs baseline: 2.0017x; 2.0017x over previous
#include <cuda_runtime.h>
#include <math.h>

#define N_VAR 50000
#define N_CLA 100000
#define NM    150000
#define DD    64
#define NC    1000
#define VC    64
#define KCL   128
#define NN    192      // nodes per cluster = VC + KCL
#define NE    8000
#define NSH   8
#define NITER 3
#define NEG   0.2f
#define GAMMA 1.0f
#define INVSCALE 0.125f   // 1/sqrt(64)
#define NWARP 16          // warps per k_attn CTA

typedef unsigned long long u64;

// packed fp32x2 FMA: d += a*b (elementwise on 2 packed floats)
__device__ __forceinline__ void fma2(u64& d, u64 a, u64 b) {
    asm("fma.rn.f32x2 %0, %1, %2, %0;" : "+l"(d) : "l"(a), "l"(b));
}
__device__ __forceinline__ float lohiadd(u64 a) {
    float lo, hi;
    asm("mov.b64 {%0,%1}, %2;" : "=f"(lo), "=f"(hi) : "l"(a));
    return lo + hi;
}
__device__ __forceinline__ u64 splat(float w) {
    u64 p; asm("mov.b64 %0, {%1,%1};" : "=l"(p) : "f"(w)); return p;
}
// swizzled quad index: row-major [row][16 quads], quad column XOR'd by row
__device__ __forceinline__ int swz(int row, int d4) { return (row << 4) + (d4 ^ (row & 15)); }

// ---------------- scratch (static device globals) ----------------------------
__device__ float g_x  [NM * DD];
__device__ float g_Q  [NM * DD];
__device__ float g_K  [NM * DD];
__device__ float g_V  [NM * DD];
__device__ float g_acc[NM * DD];
__device__ float g_cnt[NM];
__device__ float g_Q2 [NC * DD];
__device__ float g_K2 [NC * DD];
__device__ float g_V2 [NC * DD];
__device__ float g_pool[2 * DD];

__global__ void k_init(const float* __restrict__ xv, const float* __restrict__ xc) {
    int stride = gridDim.x * blockDim.x;
    for (int i = blockIdx.x * blockDim.x + threadIdx.x; i < NM * DD; i += stride)
        g_x[i] = (i < N_VAR * DD) ? xv[i] : xc[i - N_VAR * DD];
}

__global__ void k_poolzero() {
    if (threadIdx.x < 2 * DD) g_pool[threadIdx.x] = 0.f;
}

// ---------------- Q/K/V projection (+ zero g_acc/g_cnt) ----------------------
// 256 threads, 8 warps; each warp does 2 blocks of 4 rows (64 rows per CTA).
__global__ void __launch_bounds__(256) k_proj(const float* __restrict__ WQ,
                                              const float* __restrict__ WK,
                                              const float* __restrict__ WV) {
    extern __shared__ float sm[];
    float* Wt = sm;                    // 3 * 64*64, swizzled
    float* xs = sm + 3 * 64 * 64;      // 8 warps * 4 rows * 64
    int tid = threadIdx.x;
    for (int i = tid; i < 64 * 64; i += 256) {
        int j = i >> 6, k = i & 63;
        int si = (j << 6) + ((((k >> 2) ^ (j & 15)) << 2) | (k & 3));
        Wt[si]            = WQ[i];
        Wt[4096 + si]     = WK[i];
        Wt[8192 + si]     = WV[i];
    }
    __syncthreads();
    int warp = tid >> 5, lane = tid & 31;
    float* xw = xs + warp * 256;
    const ulonglong2* xw2 = (const ulonglong2*)xw;
    const ulonglong2* Wt2 = (const ulonglong2*)Wt;
    int lsw = lane & 15;

    for (int b = 0; b < 2; b++) {
        int base = blockIdx.x * 64 + warp * 8 + b * 4;
        // stage 4 rows of x
        {
            int rh = lane >> 4, qd = lane & 15;
            #pragma unroll
            for (int rr = 0; rr < 2; rr++) {
                int row = base + rr * 2 + rh;
                int rc = (row < NM) ? row : NM - 1;
                ((float4*)xw)[(rr * 2 + rh) * 16 + qd] =
                    ((const float4*)(g_x + (size_t)rc * DD))[qd];
            }
        }
        __syncwarp();
        u64 acc2[6][4];
        #pragma unroll
        for (int o = 0; o < 6; o++)
            #pragma unroll
            for (int r = 0; r < 4; r++) acc2[o][r] = 0ull;
        #pragma unroll 4
        for (int d4 = 0; d4 < 16; d4++) {
            ulonglong2 x0 = xw2[d4], x1 = xw2[16 + d4], x2 = xw2[32 + d4], x3 = xw2[48 + d4];
            int sq = (lane << 4) + (d4 ^ lsw);
            #pragma unroll
            for (int m = 0; m < 3; m++) {
                ulonglong2 wa = Wt2[m * 1024 + sq];
                ulonglong2 wb = Wt2[m * 1024 + sq + 512];
                fma2(acc2[2*m][0], wa.x, x0.x); fma2(acc2[2*m][0], wa.y, x0.y);
                fma2(acc2[2*m][1], wa.x, x1.x); fma2(acc2[2*m][1], wa.y, x1.y);
                fma2(acc2[2*m][2], wa.x, x2.x); fma2(acc2[2*m][2], wa.y, x2.y);
                fma2(acc2[2*m][3], wa.x, x3.x); fma2(acc2[2*m][3], wa.y, x3.y);
                fma2(acc2[2*m+1][0], wb.x, x0.x); fma2(acc2[2*m+1][0], wb.y, x0.y);
                fma2(acc2[2*m+1][1], wb.x, x1.x); fma2(acc2[2*m+1][1], wb.y, x1.y);
                fma2(acc2[2*m+1][2], wb.x, x2.x); fma2(acc2[2*m+1][2], wb.y, x2.y);
                fma2(acc2[2*m+1][3], wb.x, x3.x); fma2(acc2[2*m+1][3], wb.y, x3.y);
            }
        }
        #pragma unroll
        for (int r = 0; r < 4; r++) {
            int row = base + r;
            if (row >= NM) continue;
            size_t o = (size_t)row * DD;
            g_Q[o + lane]      = lohiadd(acc2[0][r]);
            g_Q[o + lane + 32] = lohiadd(acc2[1][r]);
            g_K[o + lane]      = lohiadd(acc2[2][r]);
            g_K[o + lane + 32] = lohiadd(acc2[3][r]);
            g_V[o + lane]      = lohiadd(acc2[4][r]);
            g_V[o + lane + 32] = lohiadd(acc2[5][r]);
            g_acc[o + lane] = 0.f; g_acc[o + lane + 32] = 0.f;
            if (lane == 0) g_cnt[row] = 0.f;
        }
        __syncwarp();
    }
}

// ---------------- intra-cluster attention (GAT1 core) ------------------------
// 512 threads (16 warps), 1 CTA per cluster. 4-query register blocking,
// swizzled smem tiles (stride 64), packed f32x2 FMA everywhere.
__global__ void __launch_bounds__(512, 1) k_attn(const int* __restrict__ cvar,
                                                 const int* __restrict__ ccla,
                                                 const float* __restrict__ sat,
                                                 const float* __restrict__ hw) {
    extern __shared__ float sm[];
    float* Ksh = sm;                        // NN*64 swizzled
    float* Vsh = Ksh + NN * 64;             // NN*64 swizzled
    float* qsh = Vsh + NN * 64;             // NWARP * 4 * 64
    float* wsh = qsh + NWARP * 256;         // NWARP * NN * 4
    float* bsh = wsh + NWARP * NN * 4;      // NN
    int*   nsh = (int*)(bsh + NN);          // NN

    int c = blockIdx.x, tid = threadIdx.x;
    if (tid < NN) {
        int g; float b;
        if (tid < VC) { g = cvar[c * VC + tid]; b = 0.f; }
        else { int cl = ccla[c * KCL + (tid - VC)]; g = N_VAR + cl; b = GAMMA * sat[cl]; }
        nsh[tid] = g; bsh[tid] = b;
    }
    __syncthreads();
    for (int i = tid; i < NN * DD; i += 512) {
        int j = i >> 6, d = i & 63;
        int si = (j << 6) + ((((d >> 2) ^ (j & 15)) << 2) | (d & 3));
        size_t o = (size_t)nsh[j] * DD + d;
        Ksh[si] = g_K[o];
        Vsh[si] = g_V[o];
    }
    float hwm = 0.25f * (hw[0] + hw[1] + hw[2] + hw[3]);
    __syncthreads();

    int warp = tid >> 5, lane = tid & 31;
    const ulonglong2* Ksh2 = (const ulonglong2*)Ksh;
    const ulonglong2* Vsh2 = (const ulonglong2*)Vsh;
    float* qw = qsh + warp * 256;
    const ulonglong2* qw2 = (const ulonglong2*)qw;
    float* ww = wsh + warp * NN * 4;
    int h16 = lane >> 4, l15 = lane & 15;

    float bias6[6];
    #pragma unroll
    for (int jj = 0; jj < 6; jj++) bias6[jj] = bsh[jj * 32 + lane];

    for (int b = 0; b < 3; b++) {
        int i0 = warp * 12 + b * 4;
        int gi0 = nsh[i0], gi1 = nsh[i0+1], gi2 = nsh[i0+2], gi3 = nsh[i0+3];
        // stage q for 4 rows
        {
            int rh = lane >> 4, qd = lane & 15;
            int r0 = (rh == 0) ? gi0 : gi1;
            int r1 = (rh == 0) ? gi2 : gi3;
            ((float4*)qw)[rh * 16 + qd]        = ((const float4*)(g_Q + (size_t)r0 * DD))[qd];
            ((float4*)qw)[(2 + rh) * 16 + qd]  = ((const float4*)(g_Q + (size_t)r1 * DD))[qd];
        }
        __syncwarp();

        // ---- scores: 4 query rows per warp, lane owns keys jj*32+lane ----
        u64 acc2[6][4];
        #pragma unroll
        for (int jj = 0; jj < 6; jj++)
            #pragma unroll
            for (int r = 0; r < 4; r++) acc2[jj][r] = 0ull;
        #pragma unroll 4
        for (int d4 = 0; d4 < 16; d4++) {
            ulonglong2 q0 = qw2[d4], q1 = qw2[16 + d4], q2 = qw2[32 + d4], q3 = qw2[48 + d4];
            #pragma unroll
            for (int jj = 0; jj < 6; jj++) {
                int key = jj * 32 + lane;
                ulonglong2 kk = Ksh2[(key << 4) + (d4 ^ (key & 15))];
                fma2(acc2[jj][0], kk.x, q0.x); fma2(acc2[jj][0], kk.y, q0.y);
                fma2(acc2[jj][1], kk.x, q1.x); fma2(acc2[jj][1], kk.y, q1.y);
                fma2(acc2[jj][2], kk.x, q2.x); fma2(acc2[jj][2], kk.y, q2.y);
                fma2(acc2[jj][3], kk.x, q3.x); fma2(acc2[jj][3], kk.y, q3.y);
            }
        }
        // ---- bias + leaky_relu + softmax, per row ----
        float w[6][4];
        #pragma unroll
        for (int r = 0; r < 4; r++) {
            float s[6];
            float m = -1e30f;
            #pragma unroll
            for (int jj = 0; jj < 6; jj++) {
                float v = lohiadd(acc2[jj][r]) * INVSCALE + bias6[jj];
                v = (v >= 0.f) ? v : NEG * v;
                s[jj] = v; m = fmaxf(m, v);
            }
            #pragma unroll
            for (int o = 16; o > 0; o >>= 1) m = fmaxf(m, __shfl_xor_sync(0xffffffffu, m, o));
            float ss = 0.f;
            #pragma unroll
            for (int jj = 0; jj < 6; jj++) { s[jj] = __expf(s[jj] - m); ss += s[jj]; }
            #pragma unroll
            for (int o = 16; o > 0; o >>= 1) ss += __shfl_xor_sync(0xffffffffu, ss, o);
            float inv = 1.f / ss;
            #pragma unroll
            for (int jj = 0; jj < 6; jj++) w[jj][r] = s[jj] * inv;
        }
        // ---- stage weights [key][4 rows] (STS.128 conflict-free) ----
        #pragma unroll
        for (int jj = 0; jj < 6; jj++)
            ((float4*)ww)[jj * 32 + lane] = make_float4(w[jj][0], w[jj][1], w[jj][2], w[jj][3]);
        __syncwarp();

        // ---- output: half-warp per key parity, lane quad l15; 4 rows ----
        u64 o2[4][2];
        #pragma unroll
        for (int r = 0; r < 4; r++) { o2[r][0] = 0ull; o2[r][1] = 0ull; }
        #pragma unroll 8
        for (int it = 0; it < 96; it++) {
            int key = it * 2 + h16;
            float4 w4 = ((const float4*)ww)[key];
            ulonglong2 vv = Vsh2[(key << 4) + (l15 ^ (key & 15))];
            u64 p;
            p = splat(w4.x); fma2(o2[0][0], p, vv.x); fma2(o2[0][1], p, vv.y);
            p = splat(w4.y); fma2(o2[1][0], p, vv.x); fma2(o2[1][1], p, vv.y);
            p = splat(w4.z); fma2(o2[2][0], p, vv.x); fma2(o2[2][1], p, vv.y);
            p = splat(w4.w); fma2(o2[3][0], p, vv.x); fma2(o2[3][1], p, vv.y);
        }
        int gis[4] = {gi0, gi1, gi2, gi3};
        #pragma unroll
        for (int r = 0; r < 4; r++) {
            float a0, a1, a2, a3;
            asm("mov.b64 {%0,%1}, %2;" : "=f"(a0), "=f"(a1) : "l"(o2[r][0]));
            asm("mov.b64 {%0,%1}, %2;" : "=f"(a2), "=f"(a3) : "l"(o2[r][1]));
            a0 += __shfl_xor_sync(0xffffffffu, a0, 16);
            a1 += __shfl_xor_sync(0xffffffffu, a1, 16);
            a2 += __shfl_xor_sync(0xffffffffu, a2, 16);
            a3 += __shfl_xor_sync(0xffffffffu, a3, 16);
            if (lane < 16) {
                float* dst = g_acc + (size_t)gis[r] * DD + 4 * l15;
                atomicAdd(dst + 0, a0 * hwm);
                atomicAdd(dst + 1, a1 * hwm);
                atomicAdd(dst + 2, a2 * hwm);
                atomicAdd(dst + 3, a3 * hwm);
            }
        }
        if (lane == 0) {
            atomicAdd(&g_cnt[gi0], 1.f); atomicAdd(&g_cnt[gi1], 1.f);
            atomicAdd(&g_cnt[gi2], 1.f); atomicAdd(&g_cnt[gi3], 1.f);
        }
        __syncwarp();
    }
}

// ---------------- finalize: (acc/cnt) @ Wo^T + bo, residual add --------------
__global__ void __launch_bounds__(256) k_fin(const float* __restrict__ Wo,
                                             const float* __restrict__ bo) {
    extern __shared__ float sm[];
    float* Wt = sm;                  // 64*64 swizzled
    float* xs = Wt + 64 * 64;        // 8 warps * 4 rows * 64
    int tid = threadIdx.x;
    for (int i = tid; i < 64 * 64; i += 256) {
        int j = i >> 6, k = i & 63;
        Wt[(j << 6) + ((((k >> 2) ^ (j & 15)) << 2) | (k & 3))] = Wo[i];
    }
    __syncthreads();
    int warp = tid >> 5, lane = tid & 31;
    float* xw = xs + warp * 256;
    const ulonglong2* xw2 = (const ulonglong2*)xw;
    const ulonglong2* Wt2 = (const ulonglong2*)Wt;
    float b0 = bo[lane], b1 = bo[lane + 32];
    int lsw = lane & 15;

    for (int b = 0; b < 2; b++) {
        int base = blockIdx.x * 64 + warp * 8 + b * 4;
        {
            int rh = lane >> 4, qd = lane & 15;
            #pragma unroll
            for (int rr = 0; rr < 2; rr++) {
                int row = base + rr * 2 + rh;
                int rc = (row < NM) ? row : NM - 1;
                float inv = 1.f / fmaxf(g_cnt[rc], 1.f);
                float4 a = ((const float4*)(g_acc + (size_t)rc * DD))[qd];
                a.x *= inv; a.y *= inv; a.z *= inv; a.w *= inv;
                ((float4*)xw)[(rr * 2 + rh) * 16 + qd] = a;
            }
        }
        __syncwarp();
        u64 acc2[2][4];
        #pragma unroll
        for (int o = 0; o < 2; o++)
            #pragma unroll
            for (int r = 0; r < 4; r++) acc2[o][r] = 0ull;
        #pragma unroll 4
        for (int d4 = 0; d4 < 16; d4++) {
            ulonglong2 x0 = xw2[d4], x1 = xw2[16 + d4], x2 = xw2[32 + d4], x3 = xw2[48 + d4];
            int sq = (lane << 4) + (d4 ^ lsw);
            ulonglong2 wa = Wt2[sq];
            ulonglong2 wb = Wt2[sq + 512];
            fma2(acc2[0][0], wa.x, x0.x); fma2(acc2[0][0], wa.y, x0.y);
            fma2(acc2[0][1], wa.x, x1.x); fma2(acc2[0][1], wa.y, x1.y);
            fma2(acc2[0][2], wa.x, x2.x); fma2(acc2[0][2], wa.y, x2.y);
            fma2(acc2[0][3], wa.x, x3.x); fma2(acc2[0][3], wa.y, x3.y);
            fma2(acc2[1][0], wb.x, x0.x); fma2(acc2[1][0], wb.y, x0.y);
            fma2(acc2[1][1], wb.x, x1.x); fma2(acc2[1][1], wb.y, x1.y);
            fma2(acc2[1][2], wb.x, x2.x); fma2(acc2[1][2], wb.y, x2.y);
            fma2(acc2[1][3], wb.x, x3.x); fma2(acc2[1][3], wb.y, x3.y);
        }
        #pragma unroll
        for (int r = 0; r < 4; r++) {
            int row = base + r;
            if (row >= NM) continue;
            size_t o = (size_t)row * DD;
            g_x[o + lane]      += lohiadd(acc2[0][r]) + b0;
            g_x[o + lane + 32] += lohiadd(acc2[1][r]) + b1;
        }
        __syncwarp();
    }
}

// ---------------- cluster features + Q2/K2/V2 projection ---------------------
__global__ void k_cf(const int* __restrict__ cvar,
                     const float* __restrict__ WQ2, const float* __restrict__ WK2,
                     const float* __restrict__ WV2) {
    __shared__ float cf[64];
    __shared__ int ids[64];
    int c = blockIdx.x, d = threadIdx.x;
    ids[d] = cvar[c * VC + d];
    __syncthreads();
    float s = 0.f;
    #pragma unroll 8
    for (int v = 0; v < VC; v++) s += g_x[(size_t)ids[v] * DD + d];
    cf[d] = s * (1.f / 64.f);
    __syncthreads();
    float q = 0.f, k = 0.f, v = 0.f;
    #pragma unroll 8
    for (int j = 0; j < 64; j++) {
        float x = cf[j];
        q = fmaf(x, WQ2[d * 64 + j], q);
        k = fmaf(x, WK2[d * 64 + j], k);
        v = fmaf(x, WV2[d * 64 + j], v);
    }
    g_Q2[c * 64 + d] = q; g_K2[c * 64 + d] = k; g_V2[c * 64 + d] = v;
}

// ---------------- inter-cluster edge scatter (GAT2) --------------------------
__global__ void k_edge(const int* __restrict__ ei, const int* __restrict__ shv,
                       const float* __restrict__ hw) {
    int tid = threadIdx.x;
    int warp = tid >> 5, lane = tid & 31;
    int e = blockIdx.x * 8 + warp;
    if (e >= NE) return;
    int c1 = ei[e], c2 = ei[NE + e];
    float p = g_Q2[c1 * 64 + lane] * g_K2[c2 * 64 + lane]
            + g_Q2[c1 * 64 + lane + 32] * g_K2[c2 * 64 + lane + 32];
    #pragma unroll
    for (int o = 16; o > 0; o >>= 1) p += __shfl_xor_sync(0xffffffffu, p, o);
    float s = p * INVSCALE;
    float lr = (s >= 0.f) ? s : NEG * s;
    float hwm = 0.25f * (hw[0] + hw[1] + hw[2] + hw[3]);
    float a = hwm / (1.f + __expf(-lr));
    float v0 = a * g_V2[c2 * 64 + lane];
    float v1 = a * g_V2[c2 * 64 + lane + 32];
    #pragma unroll
    for (int k = 0; k < NSH; k++) {
        int sv = shv[e * NSH + k];
        atomicAdd(&g_x[(size_t)sv * DD + lane],      v0);
        atomicAdd(&g_x[(size_t)sv * DD + lane + 32], v1);
    }
}

// ---------------- pooling + MLP readout --------------------------------------
__global__ void k_pool() {
    int tid = threadIdx.x;
    int col = tid & 63;
    int rg = tid >> 6;
    float sv = 0.f, sc = 0.f;
    for (int r = blockIdx.x * 4 + rg; r < NM; r += gridDim.x * 4) {
        float x = g_x[(size_t)r * DD + col];
        if (r < N_VAR) sv += x; else sc += x;
    }
    atomicAdd(&g_pool[col], sv);
    atomicAdd(&g_pool[64 + col], sc);
}

__global__ void k_mlp(const float* __restrict__ W1, const float* __restrict__ b1,
                      const float* __restrict__ W2, const float* __restrict__ b2,
                      float* __restrict__ out) {
    __shared__ float p[128];
    __shared__ float h[64];
    int tid = threadIdx.x;
    if (tid < 128)
        p[tid] = tanhf(g_pool[tid] * (tid < 64 ? 1.f / N_VAR : 1.f / N_CLA));
    __syncthreads();
    if (tid < 64) {
        float a = b1[tid];
        #pragma unroll 8
        for (int j = 0; j < 128; j++) a = fmaf(p[j], W1[tid * 128 + j], a);
        h[tid] = (a > 0.f) ? a : 0.f;
    }
    __syncthreads();
    if (tid == 0) {
        float s = b2[0];
        for (int i = 0; i < 64; i++) s = fmaf(h[i], W2[i], s);
        out[0] = s;
    }
}

// ---------------- launch ------------------------------------------------------
extern "C" void kernel_launch(void* const* d_in, const int* in_sizes, int n_in,
                              void* d_out, int out_size) {
    (void)in_sizes; (void)n_in; (void)out_size;
    const float* xv   = (const float*)d_in[0];
    const float* xc   = (const float*)d_in[1];
    const float* sat  = (const float*)d_in[2];
    const int*   cvar = (const int*)d_in[3];
    const int*   ccla = (const int*)d_in[4];
    const int*   ei   = (const int*)d_in[5];
    const int*   shv  = (const int*)d_in[6];
    const float* WQ1  = (const float*)d_in[7];
    const float* WK1  = (const float*)d_in[8];
    const float* WV1  = (const float*)d_in[9];
    const float* hw1  = (const float*)d_in[10];
    const float* Wo   = (const float*)d_in[11];
    const float* bo   = (const float*)d_in[12];
    const float* WQ2  = (const float*)d_in[13];
    const float* WK2  = (const float*)d_in[14];
    const float* WV2  = (const float*)d_in[15];
    const float* hw2  = (const float*)d_in[16];
    const float* W1   = (const float*)d_in[17];
    const float* b1   = (const float*)d_in[18];
    const float* W2   = (const float*)d_in[19];
    const float* b2   = (const float*)d_in[20];

    const int projSmem = (3 * 64 * 64 + 8 * 4 * 64) * 4;                        // 57344
    const int attnSmem = (2 * NN * 64 + NWARP * 256 + NWARP * NN * 4 + NN) * 4
                         + NN * 4;                                              // 165376
    const int finSmem  = (64 * 64 + 8 * 4 * 64) * 4;                            // 24576
    cudaFuncSetAttribute(k_proj, cudaFuncAttributeMaxDynamicSharedMemorySize, projSmem);
    cudaFuncSetAttribute(k_attn, cudaFuncAttributeMaxDynamicSharedMemorySize, attnSmem);

    k_init<<<512, 256>>>(xv, xc);
    const int rowBlocks = (NM + 63) / 64;
    for (int it = 0; it < NITER; it++) {
        k_proj<<<rowBlocks, 256, projSmem>>>(WQ1, WK1, WV1);   // also zeroes g_acc/g_cnt
        k_attn<<<NC, 512, attnSmem>>>(cvar, ccla, sat, hw1);
        k_fin<<<rowBlocks, 256, finSmem>>>(Wo, bo);
        k_cf<<<NC, 64>>>(cvar, WQ2, WK2, WV2);
        k_edge<<<(NE + 7) / 8, 256>>>(ei, shv, hw2);
    }
    k_poolzero<<<1, 128>>>();
    k_pool<<<512, 256>>>();
    k_mlp<<<1, 128>>>(W1, b1, W2, b2, (float*)d_out);
}